// round 12
// baseline (speedup 1.0000x reference)
#include <cuda_runtime.h>

#define N_NODES 100000
#define N_EDGES 3200000
#define F_IN    512
#define NH      16
#define NC      3

// ---------------- scratch (device globals; device-code references ONLY) -----
__device__ int   g_deg_out[N_NODES];
__device__ int   g_deg_in [N_NODES];
__device__ float g_norm_src[N_NODES];
__device__ float g_norm_dst[N_NODES];
__device__ int2  g_edge[N_EDGES];                 // packed (src,dst) int32
__device__ float g_h1  [(size_t)N_NODES * NH];    // feat@W1 (unscaled)
__device__ float g_agg1[(size_t)N_NODES * NH];
__device__ float g_y   [(size_t)N_NODES * 4];     // (relu(agg1*nd+b1)*ns)@W2f
__device__ float g_agg2[(size_t)N_NODES * 4];
__device__ float g_W2f [NH * NC];                 // W2 @ Wfc
__device__ float g_b2f [NC];                      // b2 @ Wfc + bfc
__device__ int   g_idx64;                         // 1 if indices are int64

// ---------------- index dtype detection (int64 vs int32) --------------------
__global__ void k_detect(const int* __restrict__ src_as_i32) {
    int any = 0;
    #pragma unroll
    for (int j = 0; j < 64; j++) any |= src_as_i32[2 * j + 1];
    g_idx64 = (any == 0) ? 1 : 0;
}

__device__ __forceinline__ int load_idx(const void* p, int i, int is64) {
    return is64 ? (int)((const long long*)p)[i] : ((const int*)p)[i];
}

// ---------------- zero accumulators (side stream) ----------------------------
__global__ void k_zero() {
    int i = blockIdx.x * blockDim.x + threadIdx.x;
    if (i < N_NODES * NH) g_agg1[i] = 0.f;
    if (i < N_NODES * 4)  g_agg2[i] = 0.f;
    if (i < N_NODES) { g_deg_out[i] = 0; g_deg_in[i] = 0; }
}

// ---------------- degree histogram + edge compaction (side stream) -----------
__global__ __launch_bounds__(256)
void k_deg(const void* __restrict__ src, const void* __restrict__ dst) {
    int is64 = g_idx64;
    int stride = gridDim.x * blockDim.x;
    for (int i = blockIdx.x * blockDim.x + threadIdx.x; i < N_EDGES; i += stride) {
        int s = load_idx(src, i, is64);
        int d = load_idx(dst, i, is64);
        g_edge[i] = make_int2(s, d);
        asm volatile("red.global.add.u32 [%0], %1;"
                     :: "l"(g_deg_out + s), "r"(1) : "memory");
        asm volatile("red.global.add.u32 [%0], %1;"
                     :: "l"(g_deg_in + d), "r"(1) : "memory");
    }
}

// ---------------- norms (side stream, after k_deg) ---------------------------
__global__ void k_norm() {
    int n = blockIdx.x * blockDim.x + threadIdx.x;
    if (n >= N_NODES) return;
    g_norm_src[n] = rsqrtf(fmaxf((float)g_deg_out[n], 1.f));
    g_norm_dst[n] = rsqrtf(fmaxf((float)g_deg_in [n], 1.f));
}

// ---------------- GEMM1: h1 = feat @ W1  (broadcast-W, transposed-f) ---------
// 32 nodes/block, 256 threads = 8 warps k-splitting each 64-wide chunk.
// lane = node; features staged transposed sFT[k][node] (pad 33) so the per-k
// feature read is ONE conflict-free LDS.32; the 16 W floats per k are 4
// LDS.128 at a warp-UNIFORM address => smem broadcast, 1 phase each.
// Per warp-k: 5 smem-cyc / 8 FFMA2 -> FMA/DRAM-bound (old layout: smem-bound).
// Reg-prefetch double buffer hides LDG latency; 8-way smem reduce at end.
#define GB2 32
#define KC2 64
#define NCH (F_IN / KC2)                          // 8
#define FT_STRIDE 33
#define SMEM2 ((F_IN * NH + 256 * 17) * 4)        // 32KB W + 17KB stage/reduce

__global__ __launch_bounds__(256, 4)
void k_gemm1(const float* __restrict__ feat, const float* __restrict__ W1) {
    extern __shared__ float smem[];
    float* sW   = smem;                           // [512][16]
    float* sFT  = smem + F_IN * NH;               // [64][33] (transposed chunk)
    float* sRed = smem + F_IN * NH;               // [256][17] (end reduction)

    const int tid  = threadIdx.x;
    const int w    = tid >> 5;                    // warp 0..7 (k-slice)
    const int lane = tid & 31;                    // node within block
    const int n0   = blockIdx.x * GB2;
    const int nl   = tid >> 3;                    // staging: node 0..31
    const int q0   = (tid & 7) * 2;               // staging: first float4 quad

    // W1 -> smem (coalesced float4)
    #pragma unroll
    for (int t = tid; t < F_IN * NH / 4; t += 256)
        ((float4*)sW)[t] = ((const float4*)W1)[t];

    // prefetch chunk 0 into registers (32B per thread, coalesced)
    const float* fb0 = feat + (size_t)(n0 + nl) * F_IN + q0 * 4;
    float4 r0 = *(const float4*)fb0;
    float4 r1 = *(const float4*)(fb0 + 4);

    unsigned long long A[8] = {0,0,0,0,0,0,0,0};  // 16 outputs as 8 f32x2

    for (int c = 0; c < NCH; c++) {
        __syncthreads();                          // sFT consumers done
        #pragma unroll
        for (int i = 0; i < 4; i++) {
            sFT[(q0 * 4 + i) * FT_STRIDE + nl]       = ((float*)&r0)[i];
            sFT[((q0 + 1) * 4 + i) * FT_STRIDE + nl] = ((float*)&r1)[i];
        }
        __syncthreads();                          // sFT ready
        if (c + 1 < NCH) {                        // prefetch next chunk
            const float* fb = feat + (size_t)(n0 + nl) * F_IN
                            + (c + 1) * KC2 + q0 * 4;
            r0 = *(const float4*)fb;
            r1 = *(const float4*)(fb + 4);
        }
        const float* wk = sW + (size_t)(c * KC2 + w * 8) * NH;
        const float* fk = sFT + (w * 8) * FT_STRIDE + lane;
        #pragma unroll
        for (int j = 0; j < 8; j++) {
            float f = fk[j * FT_STRIDE];
            unsigned long long fp;
            asm("mov.b64 %0, {%1, %1};" : "=l"(fp) : "f"(f));
            const ulonglong2* wp = (const ulonglong2*)(wk + j * NH);
            ulonglong2 w0 = wp[0], w1 = wp[1];    // broadcast LDS.128 x2
            asm("fma.rn.f32x2 %0, %1, %2, %0;" : "+l"(A[0]) : "l"(fp), "l"(w0.x));
            asm("fma.rn.f32x2 %0, %1, %2, %0;" : "+l"(A[1]) : "l"(fp), "l"(w0.y));
            asm("fma.rn.f32x2 %0, %1, %2, %0;" : "+l"(A[2]) : "l"(fp), "l"(w1.x));
            asm("fma.rn.f32x2 %0, %1, %2, %0;" : "+l"(A[3]) : "l"(fp), "l"(w1.y));
            const ulonglong2* wq = (const ulonglong2*)(wk + j * NH + 8);
            ulonglong2 w2 = wq[0], w3 = wq[1];    // broadcast LDS.128 x2
            asm("fma.rn.f32x2 %0, %1, %2, %0;" : "+l"(A[4]) : "l"(fp), "l"(w2.x));
            asm("fma.rn.f32x2 %0, %1, %2, %0;" : "+l"(A[5]) : "l"(fp), "l"(w2.y));
            asm("fma.rn.f32x2 %0, %1, %2, %0;" : "+l"(A[6]) : "l"(fp), "l"(w3.x));
            asm("fma.rn.f32x2 %0, %1, %2, %0;" : "+l"(A[7]) : "l"(fp), "l"(w3.y));
        }
    }

    // cross-warp reduction: sRed[warp*32+lane][17]
    __syncthreads();
    float* my = sRed + (size_t)(w * 32 + lane) * 17;
    #pragma unroll
    for (int i = 0; i < 8; i++) {
        float2 v = *(float2*)&A[i];
        my[2 * i]     = v.x;
        my[2 * i + 1] = v.y;
    }
    __syncthreads();
    int node = tid >> 3, op = tid & 7;            // node 0..31, out-pair 0..7
    float sx = 0.f, sy = 0.f;
    #pragma unroll
    for (int ww = 0; ww < 8; ww++) {
        const float* p = sRed + (size_t)(ww * 32 + node) * 17 + op * 2;
        sx += p[0]; sy += p[1];
    }
    int n = n0 + node;                            // 3125*32 == N_NODES exactly
    if (n < N_NODES)
        *(float2*)&g_h1[(size_t)n * NH + op * 2] = make_float2(sx, sy);
}

// ---------------- edge pass 1: agg1[d] += ns[s]*h1[s]  (4x RED.128) ----------
__device__ __forceinline__ void red4(float* p, float4 v) {
    asm volatile("red.global.add.v4.f32 [%0], {%1,%2,%3,%4};"
                 :: "l"(p), "f"(v.x), "f"(v.y), "f"(v.z), "f"(v.w) : "memory");
}

__global__ void k_edge1() {
    int i = blockIdx.x * blockDim.x + threadIdx.x;
    if (i >= N_EDGES) return;
    int2 e = __ldg(&g_edge[i]);
    float ns = __ldg(&g_norm_src[e.x]);
    const float4* t4 = (const float4*)(g_h1 + (size_t)e.x * NH);
    float4 v0 = __ldg(t4 + 0), v1 = __ldg(t4 + 1);
    float4 v2 = __ldg(t4 + 2), v3 = __ldg(t4 + 3);
    v0.x *= ns; v0.y *= ns; v0.z *= ns; v0.w *= ns;
    v1.x *= ns; v1.y *= ns; v1.z *= ns; v1.w *= ns;
    v2.x *= ns; v2.y *= ns; v2.z *= ns; v2.w *= ns;
    v3.x *= ns; v3.y *= ns; v3.z *= ns; v3.w *= ns;
    float* base = g_agg1 + (size_t)e.y * NH;
    red4(base + 0,  v0);
    red4(base + 4,  v1);
    red4(base + 8,  v2);
    red4(base + 12, v3);
}

// ---------------- W2f = W2 @ Wfc, b2f = b2 @ Wfc + bfc  (warp-parallel) ------
__global__ void k_w2f(const float* __restrict__ W2, const float* __restrict__ b2,
                      const float* __restrict__ Wfc, const float* __restrict__ bfc) {
    int w    = (blockIdx.x * blockDim.x + threadIdx.x) >> 5;
    int lane = threadIdx.x & 31;
    if (w < NH * NC) {
        int h = w / NC, c = w % NC;
        float s = 0.f;
        #pragma unroll
        for (int k = lane; k < 128; k += 32)
            s = fmaf(__ldg(W2 + h * 128 + k), __ldg(Wfc + k * NC + c), s);
        #pragma unroll
        for (int m = 16; m; m >>= 1) s += __shfl_xor_sync(0xffffffffu, s, m);
        if (lane == 0) g_W2f[w] = s;
    } else if (w < NH * NC + NC) {
        int c = w - NH * NC;
        float s = 0.f;
        #pragma unroll
        for (int k = lane; k < 128; k += 32)
            s = fmaf(__ldg(b2 + k), __ldg(Wfc + k * NC + c), s);
        #pragma unroll
        for (int m = 16; m; m >>= 1) s += __shfl_xor_sync(0xffffffffu, s, m);
        if (lane == 0) g_b2f[c] = s + __ldg(bfc + c);
    }
}

// ---------------- y = (relu(agg1*nd+b1)*ns) @ W2f  -> float4 (w=0) -----------
__global__ void k_y(const float* __restrict__ b1) {
    __shared__ float sw[NH * NC];
    if (threadIdx.x < NH * NC) sw[threadIdx.x] = g_W2f[threadIdx.x];
    __syncthreads();
    int n = blockIdx.x * blockDim.x + threadIdx.x;
    if (n >= N_NODES) return;
    const float4* a4 = (const float4*)(g_agg1 + (size_t)n * NH);
    float4 A[4] = {a4[0], a4[1], a4[2], a4[3]};
    const float* af = (const float*)A;
    float nd = g_norm_dst[n];
    float ns = g_norm_src[n];
    float s0 = 0.f, s1 = 0.f, s2 = 0.f;
    #pragma unroll
    for (int h = 0; h < NH; h++) {
        float x = fmaxf(fmaf(af[h], nd, __ldg(b1 + h)), 0.f) * ns;
        s0 = fmaf(x, sw[h * 3 + 0], s0);
        s1 = fmaf(x, sw[h * 3 + 1], s1);
        s2 = fmaf(x, sw[h * 3 + 2], s2);
    }
    ((float4*)g_y)[n] = make_float4(s0, s1, s2, 0.f);
}

// ---------------- edge pass 2: agg2[d] += y[s]  (1x RED.128) -----------------
__global__ void k_edge2() {
    int i = blockIdx.x * blockDim.x + threadIdx.x;
    if (i >= N_EDGES) return;
    int2 e = __ldg(&g_edge[i]);
    float4 v = __ldg((const float4*)g_y + e.x);
    red4(g_agg2 + (size_t)e.y * 4, v);
}

// ---------------- out = nd * agg2.xyz + b2f ----------------------------------
__global__ void k_out(float* __restrict__ out) {
    int n = blockIdx.x * blockDim.x + threadIdx.x;
    if (n >= N_NODES) return;
    float4 a = ((const float4*)g_agg2)[n];
    float nd = g_norm_dst[n];
    out[(size_t)n * 3 + 0] = fmaf(nd, a.x, g_b2f[0]);
    out[(size_t)n * 3 + 1] = fmaf(nd, a.y, g_b2f[1]);
    out[(size_t)n * 3 + 2] = fmaf(nd, a.z, g_b2f[2]);
}

// ---------------- launch ------------------------------------------------------
extern "C" void kernel_launch(void* const* d_in, const int* in_sizes, int n_in,
                              void* d_out, int out_size) {
    const float* feat = (const float*)d_in[0];
    const void*  src  = d_in[1];
    const void*  dst  = d_in[2];
    const float* W1   = (const float*)d_in[3];
    const float* b1   = (const float*)d_in[4];
    const float* W2   = (const float*)d_in[5];
    const float* b2   = (const float*)d_in[6];
    const float* Wfc  = (const float*)d_in[7];
    const float* bfc  = (const float*)d_in[8];
    float* out = (float*)d_out;

    static cudaStream_t s1 = nullptr;
    static cudaEvent_t  e0 = nullptr, e1 = nullptr;
    if (!s1) {
        cudaStreamCreateWithFlags(&s1, cudaStreamNonBlocking);
        cudaEventCreateWithFlags(&e0, cudaEventDisableTiming);
        cudaEventCreateWithFlags(&e1, cudaEventDisableTiming);
        cudaFuncSetAttribute(k_gemm1, cudaFuncAttributeMaxDynamicSharedMemorySize,
                             SMEM2);
    }

    const int EB = (N_EDGES + 255) / 256;            // 12500
    const int NB = (N_NODES + 255) / 256;            // 391

    // launch order arranged so k_gemm1 is the 4th launch (ncu captures #4)
    k_detect<<<1, 1>>>((const int*)src);             // #1
    cudaEventRecord(e0, 0);

    cudaStreamWaitEvent(s1, e0, 0);
    k_zero<<<(N_NODES * NH + 255) / 256, 256, 0, s1>>>();  // #2
    k_deg <<<2048, 256, 0, s1>>>(src, dst);                // #3

    k_gemm1<<<N_NODES / GB2, 256, SMEM2>>>(feat, W1);      // #4  <- profiled

    k_norm<<<NB, 256, 0, s1>>>();                          // #5
    k_w2f <<<2, 1024, 0, s1>>>(W2, b2, Wfc, bfc);          // #6
    cudaEventRecord(e1, s1);

    cudaStreamWaitEvent(0, e1, 0);
    k_edge1<<<EB, 256>>>();                                // #7
    k_y    <<<NB, 256>>>(b1);                              // #8
    k_edge2<<<EB, 256>>>();                                // #9
    k_out  <<<NB, 256>>>(out);                             // #10
}

// round 13
// speedup vs baseline: 1.0606x; 1.0606x over previous
#include <cuda_runtime.h>

#define N_NODES 100000
#define N_EDGES 3200000
#define F_IN    512
#define NH      16
#define NC      3

// ---------------- scratch (device globals; device-code references ONLY) -----
__device__ int   g_deg_out[N_NODES];
__device__ int   g_deg_in [N_NODES];
__device__ float g_norm_src[N_NODES];
__device__ float g_norm_dst[N_NODES];
__device__ int2  g_edge[N_EDGES];                 // packed (src,dst) int32
__device__ float g_h1  [(size_t)N_NODES * NH];    // feat@W1, then *= ns (k_scale)
__device__ float g_agg1[(size_t)N_NODES * NH];
__device__ float g_y   [(size_t)N_NODES * 4];     // (relu(agg1*nd+b1)*ns)@W2f
__device__ float g_agg2[(size_t)N_NODES * 4];
__device__ float g_W2f [NH * NC];                 // W2 @ Wfc
__device__ float g_b2f [NC];                      // b2 @ Wfc + bfc
__device__ int   g_idx64;                         // 1 if indices are int64

// ---------------- index dtype detection (int64 vs int32) --------------------
__global__ void k_detect(const int* __restrict__ src_as_i32) {
    int any = 0;
    #pragma unroll
    for (int j = 0; j < 64; j++) any |= src_as_i32[2 * j + 1];
    g_idx64 = (any == 0) ? 1 : 0;
}

__device__ __forceinline__ int load_idx(const void* p, int i, int is64) {
    return is64 ? (int)((const long long*)p)[i] : ((const int*)p)[i];
}

// ---------------- zero accumulators (side stream) ----------------------------
__global__ void k_zero() {
    int i = blockIdx.x * blockDim.x + threadIdx.x;
    if (i < N_NODES * NH) g_agg1[i] = 0.f;
    if (i < N_NODES * 4)  g_agg2[i] = 0.f;
    if (i < N_NODES) { g_deg_out[i] = 0; g_deg_in[i] = 0; }
}

// ---------------- degree histogram + edge compaction (side stream) -----------
__global__ __launch_bounds__(256)
void k_deg(const void* __restrict__ src, const void* __restrict__ dst) {
    int is64 = g_idx64;
    int stride = gridDim.x * blockDim.x;
    for (int i = blockIdx.x * blockDim.x + threadIdx.x; i < N_EDGES; i += stride) {
        int s = load_idx(src, i, is64);
        int d = load_idx(dst, i, is64);
        g_edge[i] = make_int2(s, d);
        asm volatile("red.global.add.u32 [%0], %1;"
                     :: "l"(g_deg_out + s), "r"(1) : "memory");
        asm volatile("red.global.add.u32 [%0], %1;"
                     :: "l"(g_deg_in + d), "r"(1) : "memory");
    }
}

// ---------------- norms (side stream, after k_deg) ---------------------------
__global__ void k_norm() {
    int n = blockIdx.x * blockDim.x + threadIdx.x;
    if (n >= N_NODES) return;
    g_norm_src[n] = rsqrtf(fmaxf((float)g_deg_out[n], 1.f));
    g_norm_dst[n] = rsqrtf(fmaxf((float)g_deg_in [n], 1.f));
}

// ---------------- GEMM1: h1 = feat @ W1  (register-direct features) ----------
// 64 nodes/block, 256 thr = 8 warps. Warp w owns k-slice {c*64+w*8 .. +8};
// lane l owns nodes l and l+32. KEY: each thread's feature working set per
// chunk (2 rows x 8 floats = 32B) is exactly its own coalesced-sector LDG --
// features NEVER touch smem. Only W1 is read from smem, at warp-uniform
// addresses (broadcast LDS.128, 1 phase). No __syncthreads in the k loop.
// Per warp/chunk: 32 LDS-phases per 128 FFMA2 (R12 layout: ~72 per 64).
// Register double-buffer hides LDG; one cross-warp smem reduce at the end.
#define GB3 64
#define RED_STRIDE 18
#define SMEM3 ((F_IN * NH + 8 * GB3 * RED_STRIDE) * 4)   // 32KB W + 36.9KB red

__global__ __launch_bounds__(256, 2)
void k_gemm1(const float* __restrict__ feat, const float* __restrict__ W1) {
    extern __shared__ float smem[];
    float* sW   = smem;                           // [512][16]
    float* sRed = smem + F_IN * NH;               // [8*64][18]

    const int tid  = threadIdx.x;
    const int w    = tid >> 5;                    // warp: k-slice owner
    const int lane = tid & 31;
    const int n0   = blockIdx.x * GB3;

    // W1 -> smem (coalesced float4)
    #pragma unroll
    for (int t = tid; t < F_IN * NH / 4; t += 256)
        ((float4*)sW)[t] = ((const float4*)W1)[t];
    __syncthreads();

    const int na = n0 + lane;                     // node a
    const int nb = n0 + 32 + lane;                // node b
    const float* ra = feat + (size_t)(na < N_NODES ? na : N_NODES - 1) * F_IN;
    const float* rb = feat + (size_t)(nb < N_NODES ? nb : N_NODES - 1) * F_IN;
    const int kw = w * 8;                         // this warp's k offset in chunk

    float4 a0 = *(const float4*)(ra + kw);
    float4 a1 = *(const float4*)(ra + kw + 4);
    float4 b0 = *(const float4*)(rb + kw);
    float4 b1 = *(const float4*)(rb + kw + 4);

    unsigned long long A[8] = {0,0,0,0,0,0,0,0};
    unsigned long long B[8] = {0,0,0,0,0,0,0,0};

    #pragma unroll
    for (int c = 0; c < 8; c++) {
        float4 na0, na1, nb0, nb1;
        if (c < 7) {                              // prefetch next chunk
            int ko = (c + 1) * 64 + kw;
            na0 = *(const float4*)(ra + ko);
            na1 = *(const float4*)(ra + ko + 4);
            nb0 = *(const float4*)(rb + ko);
            nb1 = *(const float4*)(rb + ko + 4);
        }
        float pa[8], pb[8];
        *(float4*)&pa[0] = a0; *(float4*)&pa[4] = a1;
        *(float4*)&pb[0] = b0; *(float4*)&pb[4] = b1;

        const float* wk = sW + (size_t)(c * 64 + kw) * NH;
        #pragma unroll
        for (int j = 0; j < 8; j++) {
            unsigned long long fa, fb;
            asm("mov.b64 %0, {%1, %1};" : "=l"(fa) : "f"(pa[j]));
            asm("mov.b64 %0, {%1, %1};" : "=l"(fb) : "f"(pb[j]));
            const ulonglong2* wp = (const ulonglong2*)(wk + j * NH);
            ulonglong2 w0 = wp[0], w1 = wp[1];    // broadcast LDS.128
            const ulonglong2* wq = (const ulonglong2*)(wk + j * NH + 8);
            ulonglong2 w2 = wq[0], w3 = wq[1];    // broadcast LDS.128
            asm("fma.rn.f32x2 %0, %1, %2, %0;" : "+l"(A[0]) : "l"(fa), "l"(w0.x));
            asm("fma.rn.f32x2 %0, %1, %2, %0;" : "+l"(A[1]) : "l"(fa), "l"(w0.y));
            asm("fma.rn.f32x2 %0, %1, %2, %0;" : "+l"(A[2]) : "l"(fa), "l"(w1.x));
            asm("fma.rn.f32x2 %0, %1, %2, %0;" : "+l"(A[3]) : "l"(fa), "l"(w1.y));
            asm("fma.rn.f32x2 %0, %1, %2, %0;" : "+l"(A[4]) : "l"(fa), "l"(w2.x));
            asm("fma.rn.f32x2 %0, %1, %2, %0;" : "+l"(A[5]) : "l"(fa), "l"(w2.y));
            asm("fma.rn.f32x2 %0, %1, %2, %0;" : "+l"(A[6]) : "l"(fa), "l"(w3.x));
            asm("fma.rn.f32x2 %0, %1, %2, %0;" : "+l"(A[7]) : "l"(fa), "l"(w3.y));
            asm("fma.rn.f32x2 %0, %1, %2, %0;" : "+l"(B[0]) : "l"(fb), "l"(w0.x));
            asm("fma.rn.f32x2 %0, %1, %2, %0;" : "+l"(B[1]) : "l"(fb), "l"(w0.y));
            asm("fma.rn.f32x2 %0, %1, %2, %0;" : "+l"(B[2]) : "l"(fb), "l"(w1.x));
            asm("fma.rn.f32x2 %0, %1, %2, %0;" : "+l"(B[3]) : "l"(fb), "l"(w1.y));
            asm("fma.rn.f32x2 %0, %1, %2, %0;" : "+l"(B[4]) : "l"(fb), "l"(w2.x));
            asm("fma.rn.f32x2 %0, %1, %2, %0;" : "+l"(B[5]) : "l"(fb), "l"(w2.y));
            asm("fma.rn.f32x2 %0, %1, %2, %0;" : "+l"(B[6]) : "l"(fb), "l"(w3.x));
            asm("fma.rn.f32x2 %0, %1, %2, %0;" : "+l"(B[7]) : "l"(fb), "l"(w3.y));
        }
        a0 = na0; a1 = na1; b0 = nb0; b1 = nb1;
    }

    // cross-warp reduce: partials at sRed[(w*64 + node)*18]
    __syncthreads();
    {
        float* pa = sRed + (size_t)(w * 64 + lane) * RED_STRIDE;
        float* pb = sRed + (size_t)(w * 64 + 32 + lane) * RED_STRIDE;
        #pragma unroll
        for (int i = 0; i < 8; i++) {
            *(float2*)&pa[2 * i] = *(float2*)&A[i];
            *(float2*)&pb[2 * i] = *(float2*)&B[i];
        }
    }
    __syncthreads();
    #pragma unroll
    for (int t = tid; t < GB3 * 8; t += 256) {    // (node, out-pair) tasks
        int node = t >> 3, p = t & 7;
        float sx = 0.f, sy = 0.f;
        #pragma unroll
        for (int ww = 0; ww < 8; ww++) {
            float2 v = *(float2*)&sRed[(size_t)(ww * 64 + node) * RED_STRIDE + 2 * p];
            sx += v.x; sy += v.y;
        }
        int n = n0 + node;
        if (n < N_NODES)
            *(float2*)&g_h1[(size_t)n * NH + 2 * p] = make_float2(sx, sy);
    }
}

// ---------------- scale h1 by norm_src (once, not per edge) ------------------
__global__ void k_scale() {
    int i = blockIdx.x * blockDim.x + threadIdx.x;   // one float4 of h1
    if (i >= N_NODES * 4) return;
    float ns = g_norm_src[i >> 2];
    float4 v = ((const float4*)g_h1)[i];
    v.x *= ns; v.y *= ns; v.z *= ns; v.w *= ns;
    ((float4*)g_h1)[i] = v;
}

// ---------------- edge pass 1: agg1[d] += h1s[s]  (4x RED.128) ---------------
__device__ __forceinline__ void red4(float* p, float4 v) {
    asm volatile("red.global.add.v4.f32 [%0], {%1,%2,%3,%4};"
                 :: "l"(p), "f"(v.x), "f"(v.y), "f"(v.z), "f"(v.w) : "memory");
}

__global__ void k_edge1() {
    int i = blockIdx.x * blockDim.x + threadIdx.x;
    if (i >= N_EDGES) return;
    int2 e = __ldg(&g_edge[i]);
    const float4* t4 = (const float4*)(g_h1 + (size_t)e.x * NH);
    float4 v0 = __ldg(t4 + 0), v1 = __ldg(t4 + 1);
    float4 v2 = __ldg(t4 + 2), v3 = __ldg(t4 + 3);
    float* base = g_agg1 + (size_t)e.y * NH;
    red4(base + 0,  v0);
    red4(base + 4,  v1);
    red4(base + 8,  v2);
    red4(base + 12, v3);
}

// ---------------- W2f = W2 @ Wfc, b2f = b2 @ Wfc + bfc  (warp-parallel) ------
__global__ void k_w2f(const float* __restrict__ W2, const float* __restrict__ b2,
                      const float* __restrict__ Wfc, const float* __restrict__ bfc) {
    int w    = (blockIdx.x * blockDim.x + threadIdx.x) >> 5;
    int lane = threadIdx.x & 31;
    if (w < NH * NC) {
        int h = w / NC, c = w % NC;
        float s = 0.f;
        #pragma unroll
        for (int k = lane; k < 128; k += 32)
            s = fmaf(__ldg(W2 + h * 128 + k), __ldg(Wfc + k * NC + c), s);
        #pragma unroll
        for (int m = 16; m; m >>= 1) s += __shfl_xor_sync(0xffffffffu, s, m);
        if (lane == 0) g_W2f[w] = s;
    } else if (w < NH * NC + NC) {
        int c = w - NH * NC;
        float s = 0.f;
        #pragma unroll
        for (int k = lane; k < 128; k += 32)
            s = fmaf(__ldg(b2 + k), __ldg(Wfc + k * NC + c), s);
        #pragma unroll
        for (int m = 16; m; m >>= 1) s += __shfl_xor_sync(0xffffffffu, s, m);
        if (lane == 0) g_b2f[c] = s + __ldg(bfc + c);
    }
}

// ---------------- y = (relu(agg1*nd+b1)*ns) @ W2f  -> float4 (w=0) -----------
__global__ void k_y(const float* __restrict__ b1) {
    __shared__ float sw[NH * NC];
    if (threadIdx.x < NH * NC) sw[threadIdx.x] = g_W2f[threadIdx.x];
    __syncthreads();
    int n = blockIdx.x * blockDim.x + threadIdx.x;
    if (n >= N_NODES) return;
    const float4* a4 = (const float4*)(g_agg1 + (size_t)n * NH);
    float4 A[4] = {a4[0], a4[1], a4[2], a4[3]};
    const float* af = (const float*)A;
    float nd = g_norm_dst[n];
    float ns = g_norm_src[n];
    float s0 = 0.f, s1 = 0.f, s2 = 0.f;
    #pragma unroll
    for (int h = 0; h < NH; h++) {
        float x = fmaxf(fmaf(af[h], nd, __ldg(b1 + h)), 0.f) * ns;
        s0 = fmaf(x, sw[h * 3 + 0], s0);
        s1 = fmaf(x, sw[h * 3 + 1], s1);
        s2 = fmaf(x, sw[h * 3 + 2], s2);
    }
    ((float4*)g_y)[n] = make_float4(s0, s1, s2, 0.f);
}

// ---------------- edge pass 2: agg2[d] += y[s]  (1x RED.128) -----------------
__global__ void k_edge2() {
    int i = blockIdx.x * blockDim.x + threadIdx.x;
    if (i >= N_EDGES) return;
    int2 e = __ldg(&g_edge[i]);
    float4 v = __ldg((const float4*)g_y + e.x);
    red4(g_agg2 + (size_t)e.y * 4, v);
}

// ---------------- out = nd * agg2.xyz + b2f ----------------------------------
__global__ void k_out(float* __restrict__ out) {
    int n = blockIdx.x * blockDim.x + threadIdx.x;
    if (n >= N_NODES) return;
    float4 a = ((const float4*)g_agg2)[n];
    float nd = g_norm_dst[n];
    out[(size_t)n * 3 + 0] = fmaf(nd, a.x, g_b2f[0]);
    out[(size_t)n * 3 + 1] = fmaf(nd, a.y, g_b2f[1]);
    out[(size_t)n * 3 + 2] = fmaf(nd, a.z, g_b2f[2]);
}

// ---------------- launch ------------------------------------------------------
extern "C" void kernel_launch(void* const* d_in, const int* in_sizes, int n_in,
                              void* d_out, int out_size) {
    const float* feat = (const float*)d_in[0];
    const void*  src  = d_in[1];
    const void*  dst  = d_in[2];
    const float* W1   = (const float*)d_in[3];
    const float* b1   = (const float*)d_in[4];
    const float* W2   = (const float*)d_in[5];
    const float* b2   = (const float*)d_in[6];
    const float* Wfc  = (const float*)d_in[7];
    const float* bfc  = (const float*)d_in[8];
    float* out = (float*)d_out;

    static cudaStream_t s1 = nullptr;
    static cudaEvent_t  e0 = nullptr, e1 = nullptr;
    if (!s1) {
        cudaStreamCreateWithFlags(&s1, cudaStreamNonBlocking);
        cudaEventCreateWithFlags(&e0, cudaEventDisableTiming);
        cudaEventCreateWithFlags(&e1, cudaEventDisableTiming);
        cudaFuncSetAttribute(k_gemm1, cudaFuncAttributeMaxDynamicSharedMemorySize,
                             SMEM3);
    }

    const int EB = (N_EDGES + 255) / 256;            // 12500
    const int NB = (N_NODES + 255) / 256;            // 391
    const int GBLK = (N_NODES + GB3 - 1) / GB3;      // 1563

    k_detect<<<1, 1>>>((const int*)src);             // #1
    cudaEventRecord(e0, 0);

    cudaStreamWaitEvent(s1, e0, 0);
    k_zero<<<(N_NODES * NH + 255) / 256, 256, 0, s1>>>();  // #2
    k_deg <<<2048, 256, 0, s1>>>(src, dst);                // #3

    k_gemm1<<<GBLK, 256, SMEM3>>>(feat, W1);               // #4  <- profiled

    k_norm<<<NB, 256, 0, s1>>>();                          // #5
    k_w2f <<<2, 1024, 0, s1>>>(W2, b2, Wfc, bfc);          // #6
    cudaEventRecord(e1, s1);

    cudaStreamWaitEvent(0, e1, 0);
    k_scale<<<(N_NODES * 4 + 255) / 256, 256>>>();         // #7
    k_edge1<<<EB, 256>>>();                                // #8
    k_y    <<<NB, 256>>>(b1);                              // #9
    k_edge2<<<EB, 256>>>();                                // #10
    k_out  <<<NB, 256>>>(out);                             // #11
}